// round 12
// baseline (speedup 1.0000x reference)
#include <cuda_runtime.h>
#include <math.h>

#define BB 2048
#define KK 8
#define OO 256
#define II 512

#define G  8              // o's per block (one warp each)
#define OT (OO / G)       // 32 o-tiles
#define P  8              // b-slices per (k, o-tile)  (measured optimum)

// Scratch (no allocs allowed)
__device__ int g_cnt[KK];
__device__ int g_list[KK][BB];

// ---------------------------------------------------------------------------
// 1) argmax of gumbel-perturbed logits (== hard gumbel-softmax forward
//    one-hot) + per-k compaction. 1024 threads (2 rows each). Within-k order
//    is race-nondeterministic but output values are order-independent.
// ---------------------------------------------------------------------------
__global__ __launch_bounds__(1024)
void sel_kernel(const float* __restrict__ mw,
                const float* __restrict__ u) {
    __shared__ int scnt[KK];
    const int tid = threadIdx.x;
    if (tid < KK) scnt[tid] = 0;
    __syncthreads();

    int myk[BB / 1024], mypos[BB / 1024];
#pragma unroll
    for (int r = 0; r < BB / 1024; r++) {
        const int b = tid + 1024 * r;
        float best = -INFINITY;
        int   bi   = 0;
#pragma unroll
        for (int k = 0; k < KK; k++) {
            float uv = u[b * KK + k];
            float g  = -logf(-logf(uv + 1e-10f) + 1e-10f);
            float v  = mw[k] + g;
            if (v > best) { best = v; bi = k; }   // strict > == first max (jnp.argmax)
        }
        myk[r]   = bi;
        mypos[r] = atomicAdd(&scnt[bi], 1);
    }
    __syncthreads();

#pragma unroll
    for (int r = 0; r < BB / 1024; r++)
        g_list[myk[r]][mypos[r]] = tid + 1024 * r;
    if (tid < KK) g_cnt[tid] = scnt[tid];
}

// ---------------------------------------------------------------------------
// 2) out[b,o] = sum_i X[b,i] * fmaf(exp(ls[k,o,i]), eps[b,o,i], mean[k,o,i])
//    Block = (k, o-tile, b-slice); whole block shares one k -> mean/std rows
//    in registers. TWO b's per iteration; X loads INLINED in the FMA chain
//    (L1 hits, latency covered by the eps scoreboard) to trim registers and
//    reach OCCUPANCY 3 (24 warps/SM -> +50% concurrent DRAM streams).
//    eps via __ldcs; out via __stcs. PDL gates the g_cnt/g_list reads.
// ---------------------------------------------------------------------------
__global__ __launch_bounds__(256, 3)
void main_kernel(const float* __restrict__ X,
                 const float* __restrict__ mean,
                 const float* __restrict__ ls,
                 const float* __restrict__ eps,
                 float*       __restrict__ out) {
    const int blk   = blockIdx.x;
    const int slice = blk % P;
    const int ot    = (blk / P) % OT;
    const int k     = blk / (P * OT);

    const int warp = threadIdx.x >> 5;
    const int lane = threadIdx.x & 31;
    const int o    = ot * G + warp;

    // ---- sel-independent prologue: overlaps with sel_kernel via PDL ----
    const size_t rbase = ((size_t)k * OO + o) * II;
    const float4* mrow = reinterpret_cast<const float4*>(mean + rbase);
    const float4* lrow = reinterpret_cast<const float4*>(ls   + rbase);
    float4 mv[4], sv[4];
#pragma unroll
    for (int j = 0; j < 4; j++) {
        mv[j] = mrow[lane + 32 * j];
        float4 l4 = lrow[lane + 32 * j];
        sv[j].x = expf(l4.x); sv[j].y = expf(l4.y);
        sv[j].z = expf(l4.z); sv[j].w = expf(l4.w);
    }

    // ---- wait for sel_kernel's g_cnt/g_list to be visible ----
    cudaGridDependencySynchronize();

    const int cnt   = g_cnt[k];
    const int start = (int)((long long)cnt * slice / P);
    const int end   = (int)((long long)cnt * (slice + 1) / P);
    int idx = start;

    // Odd-length remainder: one single-b iteration.
    if ((end - start) & 1) {
        const int b = g_list[k][idx++];
        const float4* ev = reinterpret_cast<const float4*>(eps + ((size_t)b * OO + o) * II);
        const float4* Xv = reinterpret_cast<const float4*>(X   + (size_t)b * II);
        float4 e4[4];
#pragma unroll
        for (int j = 0; j < 4; j++) e4[j] = __ldcs(&ev[lane + 32 * j]);
        float acc = 0.f;
#pragma unroll
        for (int j = 0; j < 4; j++) {
            const float4 x4 = Xv[lane + 32 * j];
            acc = fmaf(x4.x, fmaf(sv[j].x, e4[j].x, mv[j].x), acc);
            acc = fmaf(x4.y, fmaf(sv[j].y, e4[j].y, mv[j].y), acc);
            acc = fmaf(x4.z, fmaf(sv[j].z, e4[j].z, mv[j].z), acc);
            acc = fmaf(x4.w, fmaf(sv[j].w, e4[j].w, mv[j].w), acc);
        }
#pragma unroll
        for (int off = 16; off; off >>= 1)
            acc += __shfl_xor_sync(0xffffffffu, acc, off);
        if (lane == 0) __stcs(&out[(size_t)b * OO + o], acc);
    }

    // Main pairs: 8 eps LDG.128 in flight per warp; X inlined (L1 hits).
    for (; idx < end; idx += 2) {
        const int b0 = g_list[k][idx];
        const int b1 = g_list[k][idx + 1];
        const float4* e0 = reinterpret_cast<const float4*>(eps + ((size_t)b0 * OO + o) * II);
        const float4* e1 = reinterpret_cast<const float4*>(eps + ((size_t)b1 * OO + o) * II);
        const float4* x0 = reinterpret_cast<const float4*>(X   + (size_t)b0 * II);
        const float4* x1 = reinterpret_cast<const float4*>(X   + (size_t)b1 * II);

        float4 ea[4], eb[4];
#pragma unroll
        for (int j = 0; j < 4; j++) ea[j] = __ldcs(&e0[lane + 32 * j]);  // DRAM, evict-first
#pragma unroll
        for (int j = 0; j < 4; j++) eb[j] = __ldcs(&e1[lane + 32 * j]);  // DRAM, evict-first

        float acc0 = 0.f, acc1 = 0.f;
#pragma unroll
        for (int j = 0; j < 4; j++) {
            const float4 xa = x0[lane + 32 * j];   // L1 hit
            const float4 xb = x1[lane + 32 * j];   // L1 hit
            acc0 = fmaf(xa.x, fmaf(sv[j].x, ea[j].x, mv[j].x), acc0);
            acc1 = fmaf(xb.x, fmaf(sv[j].x, eb[j].x, mv[j].x), acc1);
            acc0 = fmaf(xa.y, fmaf(sv[j].y, ea[j].y, mv[j].y), acc0);
            acc1 = fmaf(xb.y, fmaf(sv[j].y, eb[j].y, mv[j].y), acc1);
            acc0 = fmaf(xa.z, fmaf(sv[j].z, ea[j].z, mv[j].z), acc0);
            acc1 = fmaf(xb.z, fmaf(sv[j].z, eb[j].z, mv[j].z), acc1);
            acc0 = fmaf(xa.w, fmaf(sv[j].w, ea[j].w, mv[j].w), acc0);
            acc1 = fmaf(xb.w, fmaf(sv[j].w, eb[j].w, mv[j].w), acc1);
        }
#pragma unroll
        for (int off = 16; off; off >>= 1) {
            acc0 += __shfl_xor_sync(0xffffffffu, acc0, off);
            acc1 += __shfl_xor_sync(0xffffffffu, acc1, off);
        }
        if (lane == 0) {
            __stcs(&out[(size_t)b0 * OO + o], acc0);
            __stcs(&out[(size_t)b1 * OO + o], acc1);
        }
    }
}

// ---------------------------------------------------------------------------
// Inputs (metadata order): X[B,I], mix_weights[K], mean[K,O,I],
//                          log_sigma[K,O,I], u_gumbel[B,K], eps[B,O,I]
// Output: float32 [B,O]
// ---------------------------------------------------------------------------
extern "C" void kernel_launch(void* const* d_in, const int* in_sizes, int n_in,
                              void* d_out, int out_size) {
    const float* X    = (const float*)d_in[0];
    const float* mw   = (const float*)d_in[1];
    const float* mean = (const float*)d_in[2];
    const float* ls   = (const float*)d_in[3];
    const float* u    = (const float*)d_in[4];
    const float* eps  = (const float*)d_in[5];
    float* out        = (float*)d_out;

    sel_kernel<<<1, 1024>>>(mw, u);

    // PDL launch: main starts while sel runs; prologue overlaps, body gated
    // by cudaGridDependencySynchronize().
    cudaLaunchConfig_t cfg = {};
    cfg.gridDim  = dim3(KK * OT * P);
    cfg.blockDim = dim3(256);
    cudaLaunchAttribute attr[1];
    attr[0].id = cudaLaunchAttributeProgrammaticStreamSerialization;
    attr[0].val.programmaticStreamSerializationAllowed = 1;
    cfg.attrs    = attr;
    cfg.numAttrs = 1;
    cudaLaunchKernelEx(&cfg, main_kernel, X, mean, ls, eps, out);
}

// round 13
// speedup vs baseline: 1.0244x; 1.0244x over previous
#include <cuda_runtime.h>
#include <math.h>

#define BB 2048
#define KK 8
#define OO 256
#define II 512

#define G  8              // o's per block (one warp each)
#define OT (OO / G)       // 32 o-tiles
#define P  8              // b-slices per (k, o-tile)  (measured optimum)

// Scratch (no allocs allowed)
__device__ int g_cnt[KK];
__device__ int g_list[KK][BB];

// ---------------------------------------------------------------------------
// 1) argmax of gumbel-perturbed logits (== hard gumbel-softmax forward
//    one-hot) + per-k compaction. 1024 threads (2 rows each). Within-k order
//    is race-nondeterministic but output values are order-independent.
// ---------------------------------------------------------------------------
__global__ __launch_bounds__(1024)
void sel_kernel(const float* __restrict__ mw,
                const float* __restrict__ u) {
    __shared__ int scnt[KK];
    const int tid = threadIdx.x;
    if (tid < KK) scnt[tid] = 0;
    __syncthreads();

    int myk[BB / 1024], mypos[BB / 1024];
#pragma unroll
    for (int r = 0; r < BB / 1024; r++) {
        const int b = tid + 1024 * r;
        float best = -INFINITY;
        int   bi   = 0;
#pragma unroll
        for (int k = 0; k < KK; k++) {
            float uv = u[b * KK + k];
            float g  = -logf(-logf(uv + 1e-10f) + 1e-10f);
            float v  = mw[k] + g;
            if (v > best) { best = v; bi = k; }   // strict > == first max (jnp.argmax)
        }
        myk[r]   = bi;
        mypos[r] = atomicAdd(&scnt[bi], 1);
    }
    __syncthreads();

#pragma unroll
    for (int r = 0; r < BB / 1024; r++)
        g_list[myk[r]][mypos[r]] = tid + 1024 * r;
    if (tid < KK) g_cnt[tid] = scnt[tid];
}

// ---------------------------------------------------------------------------
// 2) out[b,o] = sum_i X[b,i] * fmaf(exp(ls[k,o,i]), eps[b,o,i], mean[k,o,i])
//    R11 structure (measured optimum: 120 regs, occ 2, staged X arrays,
//    b-pairs with 8 eps LDG.128 batched). New: merged split-warp reduction —
//    acc0/acc1 folded with one cross-half exchange + 4 shared butterfly
//    levels (6 SHFL vs 10, shorter dependency chain between load batches).
//    eps via __ldcs; out via __stcs; PDL gates g_cnt/g_list reads.
// ---------------------------------------------------------------------------
__global__ __launch_bounds__(256, 2)
void main_kernel(const float* __restrict__ X,
                 const float* __restrict__ mean,
                 const float* __restrict__ ls,
                 const float* __restrict__ eps,
                 float*       __restrict__ out) {
    const int blk   = blockIdx.x;
    const int slice = blk % P;
    const int ot    = (blk / P) % OT;
    const int k     = blk / (P * OT);

    const int warp = threadIdx.x >> 5;
    const int lane = threadIdx.x & 31;
    const int o    = ot * G + warp;

    // ---- sel-independent prologue: overlaps with sel_kernel via PDL ----
    const size_t rbase = ((size_t)k * OO + o) * II;
    const float4* mrow = reinterpret_cast<const float4*>(mean + rbase);
    const float4* lrow = reinterpret_cast<const float4*>(ls   + rbase);
    float4 mv[4], sv[4];
#pragma unroll
    for (int j = 0; j < 4; j++) {
        mv[j] = mrow[lane + 32 * j];
        float4 l4 = lrow[lane + 32 * j];
        sv[j].x = expf(l4.x); sv[j].y = expf(l4.y);
        sv[j].z = expf(l4.z); sv[j].w = expf(l4.w);
    }

    // ---- wait for sel_kernel's g_cnt/g_list to be visible ----
    cudaGridDependencySynchronize();

    const int cnt   = g_cnt[k];
    const int start = (int)((long long)cnt * slice / P);
    const int end   = (int)((long long)cnt * (slice + 1) / P);
    int idx = start;

    // Odd-length remainder: one single-b iteration.
    if ((end - start) & 1) {
        const int b = g_list[k][idx++];
        const float4* ev = reinterpret_cast<const float4*>(eps + ((size_t)b * OO + o) * II);
        const float4* Xv = reinterpret_cast<const float4*>(X   + (size_t)b * II);
        float4 e4[4], x4[4];
#pragma unroll
        for (int j = 0; j < 4; j++) e4[j] = __ldcs(&ev[lane + 32 * j]);
#pragma unroll
        for (int j = 0; j < 4; j++) x4[j] = Xv[lane + 32 * j];
        float acc = 0.f;
#pragma unroll
        for (int j = 0; j < 4; j++) {
            acc = fmaf(x4[j].x, fmaf(sv[j].x, e4[j].x, mv[j].x), acc);
            acc = fmaf(x4[j].y, fmaf(sv[j].y, e4[j].y, mv[j].y), acc);
            acc = fmaf(x4[j].z, fmaf(sv[j].z, e4[j].z, mv[j].z), acc);
            acc = fmaf(x4[j].w, fmaf(sv[j].w, e4[j].w, mv[j].w), acc);
        }
#pragma unroll
        for (int off = 16; off; off >>= 1)
            acc += __shfl_xor_sync(0xffffffffu, acc, off);
        if (lane == 0) __stcs(&out[(size_t)b * OO + o], acc);
    }

    // Main pairs: 2 b's per iteration (8 eps LDG.128 in flight per warp).
    for (; idx < end; idx += 2) {
        const int b0 = g_list[k][idx];
        const int b1 = g_list[k][idx + 1];
        const float4* e0 = reinterpret_cast<const float4*>(eps + ((size_t)b0 * OO + o) * II);
        const float4* e1 = reinterpret_cast<const float4*>(eps + ((size_t)b1 * OO + o) * II);
        const float4* x0 = reinterpret_cast<const float4*>(X   + (size_t)b0 * II);
        const float4* x1 = reinterpret_cast<const float4*>(X   + (size_t)b1 * II);

        float4 ea[4], eb[4], xa[4], xb[4];
#pragma unroll
        for (int j = 0; j < 4; j++) ea[j] = __ldcs(&e0[lane + 32 * j]);  // DRAM, evict-first
#pragma unroll
        for (int j = 0; j < 4; j++) eb[j] = __ldcs(&e1[lane + 32 * j]);  // DRAM, evict-first
#pragma unroll
        for (int j = 0; j < 4; j++) xa[j] = x0[lane + 32 * j];           // L1-resident
#pragma unroll
        for (int j = 0; j < 4; j++) xb[j] = x1[lane + 32 * j];           // L1-resident

        float acc0 = 0.f, acc1 = 0.f;
#pragma unroll
        for (int j = 0; j < 4; j++) {
            acc0 = fmaf(xa[j].x, fmaf(sv[j].x, ea[j].x, mv[j].x), acc0);
            acc1 = fmaf(xb[j].x, fmaf(sv[j].x, eb[j].x, mv[j].x), acc1);
            acc0 = fmaf(xa[j].y, fmaf(sv[j].y, ea[j].y, mv[j].y), acc0);
            acc1 = fmaf(xb[j].y, fmaf(sv[j].y, eb[j].y, mv[j].y), acc1);
            acc0 = fmaf(xa[j].z, fmaf(sv[j].z, ea[j].z, mv[j].z), acc0);
            acc1 = fmaf(xb[j].z, fmaf(sv[j].z, eb[j].z, mv[j].z), acc1);
            acc0 = fmaf(xa[j].w, fmaf(sv[j].w, ea[j].w, mv[j].w), acc0);
            acc1 = fmaf(xb[j].w, fmaf(sv[j].w, eb[j].w, mv[j].w), acc1);
        }

        // Merged split-warp reduction: fold the two accumulators across the
        // half-warp boundary, then 4 shared butterfly levels. Lanes 0-15 end
        // with sum(acc0); lanes 16-31 with sum(acc1).
        float v0 = acc0 + __shfl_xor_sync(0xffffffffu, acc0, 16);
        float v1 = acc1 + __shfl_xor_sync(0xffffffffu, acc1, 16);
        float v  = (lane < 16) ? v0 : v1;
#pragma unroll
        for (int off = 8; off; off >>= 1)
            v += __shfl_xor_sync(0xffffffffu, v, off);

        if (lane == 0)       __stcs(&out[(size_t)b0 * OO + o], v);
        else if (lane == 16) __stcs(&out[(size_t)b1 * OO + o], v);
    }
}

// ---------------------------------------------------------------------------
// Inputs (metadata order): X[B,I], mix_weights[K], mean[K,O,I],
//                          log_sigma[K,O,I], u_gumbel[B,K], eps[B,O,I]
// Output: float32 [B,O]
// ---------------------------------------------------------------------------
extern "C" void kernel_launch(void* const* d_in, const int* in_sizes, int n_in,
                              void* d_out, int out_size) {
    const float* X    = (const float*)d_in[0];
    const float* mw   = (const float*)d_in[1];
    const float* mean = (const float*)d_in[2];
    const float* ls   = (const float*)d_in[3];
    const float* u    = (const float*)d_in[4];
    const float* eps  = (const float*)d_in[5];
    float* out        = (float*)d_out;

    sel_kernel<<<1, 1024>>>(mw, u);

    // PDL launch: main starts while sel runs; prologue overlaps, body gated
    // by cudaGridDependencySynchronize().
    cudaLaunchConfig_t cfg = {};
    cfg.gridDim  = dim3(KK * OT * P);
    cfg.blockDim = dim3(256);
    cudaLaunchAttribute attr[1];
    attr[0].id = cudaLaunchAttributeProgrammaticStreamSerialization;
    attr[0].val.programmaticStreamSerializationAllowed = 1;
    cfg.attrs    = attr;
    cfg.numAttrs = 1;
    cudaLaunchKernelEx(&cfg, main_kernel, X, mean, ls, eps, out);
}

// round 14
// speedup vs baseline: 1.0389x; 1.0142x over previous
#include <cuda_runtime.h>
#include <math.h>

#define BB 2048
#define KK 8
#define OO 256
#define II 512

#define G  8              // o's per block (one warp each)
#define OT (OO / G)       // 32 o-tiles
#define P  8              // b-slices per (k, o-tile)  (measured optimum)

// Scratch (no allocs allowed)
__device__ int g_cnt[KK];
__device__ int g_list[KK][BB];

// ---------------------------------------------------------------------------
// 1) argmax of gumbel-perturbed logits (== hard gumbel-softmax forward
//    one-hot) + per-k compaction. 1024 threads (2 rows each). Within-k order
//    is race-nondeterministic but output values are order-independent.
// ---------------------------------------------------------------------------
__global__ __launch_bounds__(1024)
void sel_kernel(const float* __restrict__ mw,
                const float* __restrict__ u) {
    __shared__ int scnt[KK];
    const int tid = threadIdx.x;
    if (tid < KK) scnt[tid] = 0;
    __syncthreads();

    int myk[BB / 1024], mypos[BB / 1024];
#pragma unroll
    for (int r = 0; r < BB / 1024; r++) {
        const int b = tid + 1024 * r;
        float best = -INFINITY;
        int   bi   = 0;
#pragma unroll
        for (int k = 0; k < KK; k++) {
            float uv = u[b * KK + k];
            float g  = -logf(-logf(uv + 1e-10f) + 1e-10f);
            float v  = mw[k] + g;
            if (v > best) { best = v; bi = k; }   // strict > == first max (jnp.argmax)
        }
        myk[r]   = bi;
        mypos[r] = atomicAdd(&scnt[bi], 1);
    }
    __syncthreads();

#pragma unroll
    for (int r = 0; r < BB / 1024; r++)
        g_list[myk[r]][mypos[r]] = tid + 1024 * r;
    if (tid < KK) g_cnt[tid] = scnt[tid];
}

// ---------------------------------------------------------------------------
// 2) out[b,o] = sum_i X[b,i] * fmaf(exp(ls[k,o,i]), eps[b,o,i], mean[k,o,i])
//    R11 structure (measured optimum: 120 regs, occ 2, staged X arrays,
//    b-pairs with 8 eps LDG.128 batched, dual 5-level butterfly reduce).
//    New: software-pipelined g_list index prefetch — next pair's b-indices
//    loaded during the current FMA phase, removing the dependent
//    index-load + address-math bubble from each iteration head.
//    eps via __ldcs; out via __stcs; PDL gates g_cnt/g_list reads.
// ---------------------------------------------------------------------------
__global__ __launch_bounds__(256, 2)
void main_kernel(const float* __restrict__ X,
                 const float* __restrict__ mean,
                 const float* __restrict__ ls,
                 const float* __restrict__ eps,
                 float*       __restrict__ out) {
    const int blk   = blockIdx.x;
    const int slice = blk % P;
    const int ot    = (blk / P) % OT;
    const int k     = blk / (P * OT);

    const int warp = threadIdx.x >> 5;
    const int lane = threadIdx.x & 31;
    const int o    = ot * G + warp;

    // ---- sel-independent prologue: overlaps with sel_kernel via PDL ----
    const size_t rbase = ((size_t)k * OO + o) * II;
    const float4* mrow = reinterpret_cast<const float4*>(mean + rbase);
    const float4* lrow = reinterpret_cast<const float4*>(ls   + rbase);
    float4 mv[4], sv[4];
#pragma unroll
    for (int j = 0; j < 4; j++) {
        mv[j] = mrow[lane + 32 * j];
        float4 l4 = lrow[lane + 32 * j];
        sv[j].x = expf(l4.x); sv[j].y = expf(l4.y);
        sv[j].z = expf(l4.z); sv[j].w = expf(l4.w);
    }

    // ---- wait for sel_kernel's g_cnt/g_list to be visible ----
    cudaGridDependencySynchronize();

    const int cnt   = g_cnt[k];
    const int start = (int)((long long)cnt * slice / P);
    const int end   = (int)((long long)cnt * (slice + 1) / P);
    int idx = start;

    // Odd-length remainder: one single-b iteration.
    if ((end - start) & 1) {
        const int b = g_list[k][idx++];
        const float4* ev = reinterpret_cast<const float4*>(eps + ((size_t)b * OO + o) * II);
        const float4* Xv = reinterpret_cast<const float4*>(X   + (size_t)b * II);
        float4 e4[4], x4[4];
#pragma unroll
        for (int j = 0; j < 4; j++) e4[j] = __ldcs(&ev[lane + 32 * j]);
#pragma unroll
        for (int j = 0; j < 4; j++) x4[j] = Xv[lane + 32 * j];
        float acc = 0.f;
#pragma unroll
        for (int j = 0; j < 4; j++) {
            acc = fmaf(x4[j].x, fmaf(sv[j].x, e4[j].x, mv[j].x), acc);
            acc = fmaf(x4[j].y, fmaf(sv[j].y, e4[j].y, mv[j].y), acc);
            acc = fmaf(x4[j].z, fmaf(sv[j].z, e4[j].z, mv[j].z), acc);
            acc = fmaf(x4[j].w, fmaf(sv[j].w, e4[j].w, mv[j].w), acc);
        }
#pragma unroll
        for (int off = 16; off; off >>= 1)
            acc += __shfl_xor_sync(0xffffffffu, acc, off);
        if (lane == 0) __stcs(&out[(size_t)b * OO + o], acc);
    }

    // Main pairs with index prefetch: 8 eps LDG.128 in flight per warp.
    int b0 = 0, b1 = 0;
    if (idx < end) { b0 = g_list[k][idx]; b1 = g_list[k][idx + 1]; }

    for (; idx < end; idx += 2) {
        const float4* e0 = reinterpret_cast<const float4*>(eps + ((size_t)b0 * OO + o) * II);
        const float4* e1 = reinterpret_cast<const float4*>(eps + ((size_t)b1 * OO + o) * II);
        const float4* x0 = reinterpret_cast<const float4*>(X   + (size_t)b0 * II);
        const float4* x1 = reinterpret_cast<const float4*>(X   + (size_t)b1 * II);

        float4 ea[4], eb[4], xa[4], xb[4];
#pragma unroll
        for (int j = 0; j < 4; j++) ea[j] = __ldcs(&e0[lane + 32 * j]);  // DRAM, evict-first
#pragma unroll
        for (int j = 0; j < 4; j++) eb[j] = __ldcs(&e1[lane + 32 * j]);  // DRAM, evict-first
#pragma unroll
        for (int j = 0; j < 4; j++) xa[j] = x0[lane + 32 * j];           // L1-resident
#pragma unroll
        for (int j = 0; j < 4; j++) xb[j] = x1[lane + 32 * j];           // L1-resident

        const int bc0 = b0, bc1 = b1;
        // Prefetch next pair's indices during the FMA phase.
        if (idx + 2 < end) { b0 = g_list[k][idx + 2]; b1 = g_list[k][idx + 3]; }

        float acc0 = 0.f, acc1 = 0.f;
#pragma unroll
        for (int j = 0; j < 4; j++) {
            acc0 = fmaf(xa[j].x, fmaf(sv[j].x, ea[j].x, mv[j].x), acc0);
            acc1 = fmaf(xb[j].x, fmaf(sv[j].x, eb[j].x, mv[j].x), acc1);
            acc0 = fmaf(xa[j].y, fmaf(sv[j].y, ea[j].y, mv[j].y), acc0);
            acc1 = fmaf(xb[j].y, fmaf(sv[j].y, eb[j].y, mv[j].y), acc1);
            acc0 = fmaf(xa[j].z, fmaf(sv[j].z, ea[j].z, mv[j].z), acc0);
            acc1 = fmaf(xb[j].z, fmaf(sv[j].z, eb[j].z, mv[j].z), acc1);
            acc0 = fmaf(xa[j].w, fmaf(sv[j].w, ea[j].w, mv[j].w), acc0);
            acc1 = fmaf(xb[j].w, fmaf(sv[j].w, eb[j].w, mv[j].w), acc1);
        }
#pragma unroll
        for (int off = 16; off; off >>= 1) {
            acc0 += __shfl_xor_sync(0xffffffffu, acc0, off);
            acc1 += __shfl_xor_sync(0xffffffffu, acc1, off);
        }
        if (lane == 0) {
            __stcs(&out[(size_t)bc0 * OO + o], acc0);
            __stcs(&out[(size_t)bc1 * OO + o], acc1);
        }
    }
}

// ---------------------------------------------------------------------------
// Inputs (metadata order): X[B,I], mix_weights[K], mean[K,O,I],
//                          log_sigma[K,O,I], u_gumbel[B,K], eps[B,O,I]
// Output: float32 [B,O]
// ---------------------------------------------------------------------------
extern "C" void kernel_launch(void* const* d_in, const int* in_sizes, int n_in,
                              void* d_out, int out_size) {
    const float* X    = (const float*)d_in[0];
    const float* mw   = (const float*)d_in[1];
    const float* mean = (const float*)d_in[2];
    const float* ls   = (const float*)d_in[3];
    const float* u    = (const float*)d_in[4];
    const float* eps  = (const float*)d_in[5];
    float* out        = (float*)d_out;

    sel_kernel<<<1, 1024>>>(mw, u);

    // PDL launch: main starts while sel runs; prologue overlaps, body gated
    // by cudaGridDependencySynchronize().
    cudaLaunchConfig_t cfg = {};
    cfg.gridDim  = dim3(KK * OT * P);
    cfg.blockDim = dim3(256);
    cudaLaunchAttribute attr[1];
    attr[0].id = cudaLaunchAttributeProgrammaticStreamSerialization;
    attr[0].val.programmaticStreamSerializationAllowed = 1;
    cfg.attrs    = attr;
    cfg.numAttrs = 1;
    cudaLaunchKernelEx(&cfg, main_kernel, X, mean, ls, eps, out);
}